// round 7
// baseline (speedup 1.0000x reference)
#include <cuda_runtime.h>
#include <cstdint>

#define B_SZ 512
#define I_SZ 256
#define H_SZ 512
#define ICH  8

// Transformed parameter planes (recurrent + sensory) and scratch
__device__ float g_SG[H_SZ*H_SZ];
__device__ float g_MS[H_SZ*H_SZ];
__device__ float g_WE[H_SZ*H_SZ];
__device__ float g_WW[H_SZ*H_SZ];
__device__ float s_SG[I_SZ*H_SZ];
__device__ float s_MS[I_SZ*H_SZ];
__device__ float s_WE[I_SZ*H_SZ];
__device__ float s_WW[I_SZ*H_SZ];
__device__ float g_CN[H_SZ];
__device__ float g_CD[H_SZ];
__device__ float g_A [B_SZ*H_SZ];
__device__ float g_Dc[B_SZ*H_SZ];
__device__ float g_v0[B_SZ*H_SZ];
__device__ float g_v1[B_SZ*H_SZ];

__device__ __forceinline__ float tanh_fast(float x){
    float y;
    asm("tanh.approx.f32 %0, %1;" : "=f"(y) : "f"(x));
    return y;
}

// sigmoid((v-mu)*sigma) = 0.5*tanh(0.5*sigma*v - 0.5*sigma*mu) + 0.5
__global__ void k_prep(const float* __restrict__ mu, const float* __restrict__ sigma,
                       const float* __restrict__ W,  const float* __restrict__ erev,
                       const float* __restrict__ smu, const float* __restrict__ ssig,
                       const float* __restrict__ sW,  const float* __restrict__ serev){
    int idx = blockIdx.x*blockDim.x + threadIdx.x;
    if (idx < H_SZ*H_SZ){
        float s = sigma[idx], m = mu[idx], w = W[idx], e = erev[idx];
        g_SG[idx] = 0.5f*s;
        g_MS[idx] = -0.5f*s*m;
        g_WE[idx] = 0.5f*w*e;
        g_WW[idx] = 0.5f*w;
    } else if (idx < (H_SZ + I_SZ)*H_SZ){
        int j = idx - H_SZ*H_SZ;
        float s = ssig[j], m = smu[j], w = sW[j], e = serev[j];
        s_SG[j] = 0.5f*s;
        s_MS[j] = -0.5f*s*m;
        s_WE[j] = 0.5f*w*e;
        s_WW[j] = 0.5f*w;
    }
}

// Per-h constants: column sums of WE/WW over recurrent (H) + sensory (I) rows
__global__ void k_colsum(){
    int h0 = blockIdx.x * 32;
    int hh = threadIdx.x & 31;
    int it = threadIdx.x >> 5;
    float sn = 0.f, sd = 0.f;
    for (int i = it; i < H_SZ; i += 8){
        sn += g_WE[i*H_SZ + h0 + hh];
        sd += g_WW[i*H_SZ + h0 + hh];
    }
    for (int i = it; i < I_SZ; i += 8){
        sn += s_WE[i*H_SZ + h0 + hh];
        sd += s_WW[i*H_SZ + h0 + hh];
    }
    __shared__ float rn[8][32], rd[8][32];
    rn[it][hh] = sn; rd[it][hh] = sd;
    __syncthreads();
    if (it == 0){
        float a = 0.f, b = 0.f;
        #pragma unroll
        for (int k = 0; k < 8; k++){ a += rn[k][hh]; b += rd[k][hh]; }
        g_CN[h0+hh] = a; g_CD[h0+hh] = b;
    }
}

// ---------------------------------------------------------------------------
// Main loop core, i-split within block. Tile 64h x 8b, 256 threads
// = 2 halves x 4 warps. Half hf reduces i in [hf*HALF_I, (hf+1)*HALF_I).
// Lane covers h = h0+2*lane+{0,1} (conflict-free LDS.64 params).
// Warp-in-half covers 2 batches. Register double-buffer, 1 barrier/chunk.
// f32 tanh (1 MUFU per element).
// ---------------------------------------------------------------------------
template<int HALF_I, int VSTR>
__device__ __forceinline__ void mainloop_core(
        const float* __restrict__ P0, const float* __restrict__ P1,
        const float* __restrict__ P2, const float* __restrict__ P3,
        const float* __restrict__ vin, int h0, int b0, int tx,
        float (&num)[2][2], float (&den)[2][2],
        float (*sp)[2][4][ICH][64], float (*vs)[2][8][ICH+1])
{
    const int hf   = tx >> 7;          // half: 0/1
    const int txh  = tx & 127;
    const int lane = tx & 31;
    const int wq   = (txh >> 5);       // warp in half: 0..3 -> b = b0+2*wq+{0,1}
    const int ibase = hf * HALF_I;
    const int pic  = txh >> 4;         // 0..7   (prefetch ic)
    const int pq   = (txh & 15) * 4;   // 0..60  (prefetch h-quad)
    const int vrow = txh >> 3;         // 0..15 (only 0..7 used)
    const int vq   = txh & 7;          // 0..7
    const int NC   = HALF_I / ICH;

    float4 r[4];
    float rv;

    auto prefetch = [&](int c){
        int i0 = ibase + c * ICH;
        int g  = (i0 + pic)*H_SZ + h0 + pq;
        r[0] = *(const float4*)&P0[g];
        r[1] = *(const float4*)&P1[g];
        r[2] = *(const float4*)&P2[g];
        r[3] = *(const float4*)&P3[g];
        if (txh < 64) rv = vin[(b0 + vrow)*VSTR + i0 + vq];
    };
    auto sts = [&](int buf){
        *(float4*)&sp[hf][buf][0][pic][pq] = r[0];
        *(float4*)&sp[hf][buf][1][pic][pq] = r[1];
        *(float4*)&sp[hf][buf][2][pic][pq] = r[2];
        *(float4*)&sp[hf][buf][3][pic][pq] = r[3];
        if (txh < 64) vs[hf][buf][vrow][vq] = rv;
    };

    int buf = 0;
    prefetch(0); sts(0); __syncthreads();

    for (int c = 0; c < NC; c++){
        if (c + 1 < NC) prefetch(c + 1);
        #pragma unroll
        for (int ic = 0; ic < ICH; ic++){
            float2 SG = *(const float2*)&sp[hf][buf][0][ic][2*lane];
            float2 MS = *(const float2*)&sp[hf][buf][1][ic][2*lane];
            float2 WE = *(const float2*)&sp[hf][buf][2][ic][2*lane];
            float2 WW = *(const float2*)&sp[hf][buf][3][ic][2*lane];
            #pragma unroll
            for (int j = 0; j < 2; j++){
                float v = vs[hf][buf][2*wq + j][ic];
                float t0 = tanh_fast(fmaf(v, SG.x, MS.x));
                float t1 = tanh_fast(fmaf(v, SG.y, MS.y));
                num[j][0] = fmaf(WE.x, t0, num[j][0]);
                den[j][0] = fmaf(WW.x, t0, den[j][0]);
                num[j][1] = fmaf(WE.y, t1, num[j][1]);
                den[j][1] = fmaf(WW.y, t1, den[j][1]);
            }
        }
        if (c + 1 < NC){ sts(buf ^ 1); __syncthreads(); buf ^= 1; }
    }

    // Combine halves: half 1 stores partials, half 0 adds them.
    __syncthreads();
    float* red = &sp[0][0][0][0][0];    // reuse SMEM (needs 1024 floats)
    if (hf == 1){
        #pragma unroll
        for (int j = 0; j < 2; j++){
            #pragma unroll
            for (int k = 0; k < 2; k++){
                red[txh*8 + j*2 + k]     = num[j][k];
                red[txh*8 + j*2 + k + 4] = den[j][k];
            }
        }
    }
    __syncthreads();
    if (hf == 0){
        #pragma unroll
        for (int j = 0; j < 2; j++){
            #pragma unroll
            for (int k = 0; k < 2; k++){
                num[j][k] += red[txh*8 + j*2 + k];
                den[j][k] += red[txh*8 + j*2 + k + 4];
            }
        }
    }
}

// ---------------------------------------------------------------------------
// Sensory pass: writes A[b,h], Dc[b,h] with all constants folded in.
// ---------------------------------------------------------------------------
__global__ __launch_bounds__(256) void k_sensory(
        const float* __restrict__ inp,
        const float* __restrict__ vleak, const float* __restrict__ gleak,
        const float* __restrict__ cm){
    __shared__ __align__(16) float sp[2][2][4][ICH][64];
    __shared__ float vs[2][2][8][ICH+1];

    const int h0 = blockIdx.x * 64;
    const int b0 = blockIdx.y * 8;
    const int tx = threadIdx.x;

    float num[2][2] = {}, den[2][2] = {};
    mainloop_core<I_SZ/2, I_SZ>(s_SG, s_MS, s_WE, s_WW, inp, h0, b0, tx,
                                num, den, sp, vs);

    if (tx < 128){
        const int lane = tx & 31;
        const int wq   = tx >> 5;
        #pragma unroll
        for (int k = 0; k < 2; k++){
            int h = h0 + 2*lane + k;
            float base_n = fmaf(gleak[h], vleak[h], g_CN[h]);
            float base_d = cm[h] + gleak[h] + g_CD[h];
            #pragma unroll
            for (int j = 0; j < 2; j++){
                int b = b0 + 2*wq + j;
                g_A [b*H_SZ + h] = num[j][k] + base_n;
                g_Dc[b*H_SZ + h] = den[j][k] + base_d;
            }
        }
    }
}

// ---------------------------------------------------------------------------
// One recurrent unfold.
// ---------------------------------------------------------------------------
__global__ __launch_bounds__(256) void k_step(const float* vext, float* voutext,
                                              int sel_in, int sel_out,
                                              const float* __restrict__ cm){
    const float* vin  = (sel_in  == 0) ? g_v0 : ((sel_in  == 1) ? g_v1 : vext);
    float*       vout = (sel_out == 0) ? g_v0 : ((sel_out == 1) ? g_v1 : voutext);

    __shared__ __align__(16) float sp[2][2][4][ICH][64];
    __shared__ float vs[2][2][8][ICH+1];

    const int h0 = blockIdx.x * 64;
    const int b0 = blockIdx.y * 8;
    const int tx = threadIdx.x;

    float num[2][2] = {}, den[2][2] = {};
    mainloop_core<H_SZ/2, H_SZ>(g_SG, g_MS, g_WE, g_WW, vin, h0, b0, tx,
                                num, den, sp, vs);

    if (tx < 128){
        const int lane = tx & 31;
        const int wq   = tx >> 5;
        #pragma unroll
        for (int k = 0; k < 2; k++){
            int h = h0 + 2*lane + k;
            float cmh = cm[h];
            #pragma unroll
            for (int j = 0; j < 2; j++){
                int b = b0 + 2*wq + j;
                float n = fmaf(cmh, vin[b*H_SZ + h], g_A[b*H_SZ + h]) + num[j][k];
                float d = g_Dc[b*H_SZ + h] + den[j][k];
                vout[b*H_SZ + h] = __fdividef(n, d + 1e-8f);
            }
        }
    }
}

extern "C" void kernel_launch(void* const* d_in, const int* in_sizes, int n_in,
                              void* d_out, int out_size){
    const float* inputs = (const float*)d_in[0];
    const float* state  = (const float*)d_in[1];
    const float* smu    = (const float*)d_in[2];
    const float* ssig   = (const float*)d_in[3];
    const float* sW     = (const float*)d_in[4];
    const float* serev  = (const float*)d_in[5];
    const float* mu     = (const float*)d_in[6];
    const float* sigma  = (const float*)d_in[7];
    const float* W      = (const float*)d_in[8];
    const float* erev   = (const float*)d_in[9];
    const float* vleak  = (const float*)d_in[10];
    const float* gleak  = (const float*)d_in[11];
    const float* cm     = (const float*)d_in[12];
    float* out = (float*)d_out;

    k_prep<<<((H_SZ+I_SZ)*H_SZ + 255)/256, 256>>>(mu, sigma, W, erev,
                                                  smu, ssig, sW, serev);
    k_colsum<<<H_SZ/32, 256>>>();

    dim3 grid(H_SZ/64, B_SZ/8);   // (8, 64) = 512 blocks, 256 threads each
    k_sensory<<<grid, 256>>>(inputs, vleak, gleak, cm);

    // 6 unfolds: state -> v0 -> v1 -> v0 -> v1 -> v0 -> out
    k_step<<<grid, 256>>>(state,   nullptr, 2, 0, cm);
    k_step<<<grid, 256>>>(nullptr, nullptr, 0, 1, cm);
    k_step<<<grid, 256>>>(nullptr, nullptr, 1, 0, cm);
    k_step<<<grid, 256>>>(nullptr, nullptr, 0, 1, cm);
    k_step<<<grid, 256>>>(nullptr, nullptr, 1, 0, cm);
    k_step<<<grid, 256>>>(nullptr, out,     0, 2, cm);
}

// round 8
// speedup vs baseline: 1.2439x; 1.2439x over previous
#include <cuda_runtime.h>
#include <cstdint>

#define B_SZ 512
#define I_SZ 256
#define H_SZ 512
#define ICH  4

// Transformed parameter planes (recurrent + sensory) and scratch
__device__ float g_SG[H_SZ*H_SZ];
__device__ float g_MS[H_SZ*H_SZ];
__device__ float g_WE[H_SZ*H_SZ];
__device__ float g_WW[H_SZ*H_SZ];
__device__ float s_SG[I_SZ*H_SZ];
__device__ float s_MS[I_SZ*H_SZ];
__device__ float s_WE[I_SZ*H_SZ];
__device__ float s_WW[I_SZ*H_SZ];
__device__ float g_CN[H_SZ];
__device__ float g_CD[H_SZ];
__device__ float g_A [B_SZ*H_SZ];
__device__ float g_Dc[B_SZ*H_SZ];
__device__ float g_v0[B_SZ*H_SZ];
__device__ float g_v1[B_SZ*H_SZ];

__device__ __forceinline__ float tanh_fast(float x){
    float y;
    asm("tanh.approx.f32 %0, %1;" : "=f"(y) : "f"(x));
    return y;
}
__device__ __forceinline__ uint32_t saddr(const void* p){
    return (uint32_t)__cvta_generic_to_shared(p);
}
__device__ __forceinline__ void cp16(uint32_t dst, const void* src){
    asm volatile("cp.async.ca.shared.global [%0], [%1], 16;" :: "r"(dst), "l"(src));
}
__device__ __forceinline__ void cp4(uint32_t dst, const void* src){
    asm volatile("cp.async.ca.shared.global [%0], [%1], 4;" :: "r"(dst), "l"(src));
}

// sigmoid((v-mu)*sigma) = 0.5*tanh(0.5*sigma*v - 0.5*sigma*mu) + 0.5
__global__ void k_prep(const float* __restrict__ mu, const float* __restrict__ sigma,
                       const float* __restrict__ W,  const float* __restrict__ erev,
                       const float* __restrict__ smu, const float* __restrict__ ssig,
                       const float* __restrict__ sW,  const float* __restrict__ serev){
    int idx = blockIdx.x*blockDim.x + threadIdx.x;
    if (idx < H_SZ*H_SZ){
        float s = sigma[idx], m = mu[idx], w = W[idx], e = erev[idx];
        g_SG[idx] = 0.5f*s;
        g_MS[idx] = -0.5f*s*m;
        g_WE[idx] = 0.5f*w*e;
        g_WW[idx] = 0.5f*w;
    } else if (idx < (H_SZ + I_SZ)*H_SZ){
        int j = idx - H_SZ*H_SZ;
        float s = ssig[j], m = smu[j], w = sW[j], e = serev[j];
        s_SG[j] = 0.5f*s;
        s_MS[j] = -0.5f*s*m;
        s_WE[j] = 0.5f*w*e;
        s_WW[j] = 0.5f*w;
    }
}

// Per-h constants: column sums of WE/WW over recurrent (H) + sensory (I) rows
__global__ void k_colsum(){
    int h0 = blockIdx.x * 32;
    int hh = threadIdx.x & 31;
    int it = threadIdx.x >> 5;
    float sn = 0.f, sd = 0.f;
    for (int i = it; i < H_SZ; i += 8){
        sn += g_WE[i*H_SZ + h0 + hh];
        sd += g_WW[i*H_SZ + h0 + hh];
    }
    for (int i = it; i < I_SZ; i += 8){
        sn += s_WE[i*H_SZ + h0 + hh];
        sd += s_WW[i*H_SZ + h0 + hh];
    }
    __shared__ float rn[8][32], rd[8][32];
    rn[it][hh] = sn; rd[it][hh] = sd;
    __syncthreads();
    if (it == 0){
        float a = 0.f, b = 0.f;
        #pragma unroll
        for (int k = 0; k < 8; k++){ a += rn[k][hh]; b += rd[k][hh]; }
        g_CN[h0+hh] = a; g_CD[h0+hh] = b;
    }
}

// ---------------------------------------------------------------------------
// Main loop core. Tile 64h x 16b, 512 threads = 4 quarters x 4 warps.
// Quarter qt reduces i in [qt*QI, (qt+1)*QI). Lane covers h=h0+2*lane+{0,1}
// (conflict-free LDS.64 params); warp-in-quarter covers 4 batches.
// Staging via cp.async double buffer, 1 barrier per chunk. f32 tanh.
// 4-way partial combine in SMEM at the end (result valid for tx < 128).
// ---------------------------------------------------------------------------
template<int QI, int VSTR>
__device__ __forceinline__ void mainloop_core(
        const float* __restrict__ P0, const float* __restrict__ P1,
        const float* __restrict__ P2, const float* __restrict__ P3,
        const float* __restrict__ vin, int h0, int b0, int tx,
        float (&num)[4][2], float (&den)[4][2],
        float (*sp)[2][4][ICH][64], float (*vs)[2][16][ICH+1])
{
    const int qt   = tx >> 7;          // quarter 0..3
    const int txq  = tx & 127;
    const int lane = tx & 31;
    const int wq   = txq >> 5;         // warp in quarter: b = b0 + 4*wq + j
    const int ibase = qt * QI;
    const int NC   = QI / ICH;

    // param cp mapping: 2 x 16B per thread covers 4 planes x ICH x 64 floats
    const int pl0  = txq >> 6;               // k=0 -> planes 0,1
    const int rem  = txq & 63;
    const int prow = rem >> 4;               // 0..3
    const int pcol = (rem & 15) * 4;         // 0..60
    // v cp mapping (txq < 64): 16 rows x 4 i
    const int vrow = txq >> 2;
    const int vq   = txq & 3;

    auto issue = [&](int c, int buf){
        int i0 = ibase + c * ICH;
        {
            const float* s0 = ((pl0 == 0) ? P0 : P1) + (i0 + prow)*H_SZ + h0 + pcol;
            cp16(saddr(&sp[qt][buf][pl0][prow][pcol]), s0);
            const float* s1 = ((pl0 == 0) ? P2 : P3) + (i0 + prow)*H_SZ + h0 + pcol;
            cp16(saddr(&sp[qt][buf][pl0 + 2][prow][pcol]), s1);
        }
        if (txq < 64)
            cp4(saddr(&vs[qt][buf][vrow][vq]), &vin[(b0 + vrow)*VSTR + i0 + vq]);
        asm volatile("cp.async.commit_group;");
    };

    int buf = 0;
    issue(0, 0);
    asm volatile("cp.async.wait_group 0;");
    __syncthreads();

    for (int c = 0; c < NC; c++){
        if (c + 1 < NC) issue(c + 1, buf ^ 1);
        #pragma unroll
        for (int ic = 0; ic < ICH; ic++){
            float2 SG = *(const float2*)&sp[qt][buf][0][ic][2*lane];
            float2 MS = *(const float2*)&sp[qt][buf][1][ic][2*lane];
            float2 WE = *(const float2*)&sp[qt][buf][2][ic][2*lane];
            float2 WW = *(const float2*)&sp[qt][buf][3][ic][2*lane];
            #pragma unroll
            for (int j = 0; j < 4; j++){
                float v = vs[qt][buf][4*wq + j][ic];
                float t0 = tanh_fast(fmaf(v, SG.x, MS.x));
                float t1 = tanh_fast(fmaf(v, SG.y, MS.y));
                num[j][0] = fmaf(WE.x, t0, num[j][0]);
                den[j][0] = fmaf(WW.x, t0, den[j][0]);
                num[j][1] = fmaf(WE.y, t1, num[j][1]);
                den[j][1] = fmaf(WW.y, t1, den[j][1]);
            }
        }
        if (c + 1 < NC){
            asm volatile("cp.async.wait_group 0;");
            __syncthreads();
            buf ^= 1;
        }
    }

    // Combine quarters: 1..3 store partials, quarter 0 accumulates.
    __syncthreads();
    float* red = &sp[0][0][0][0][0];    // reuse SMEM (needs 3*2048 floats)
    if (qt > 0){
        #pragma unroll
        for (int j = 0; j < 4; j++){
            #pragma unroll
            for (int k = 0; k < 2; k++){
                red[(qt-1)*2048 + txq*16 + j*2 + k]     = num[j][k];
                red[(qt-1)*2048 + txq*16 + j*2 + k + 8] = den[j][k];
            }
        }
    }
    __syncthreads();
    if (qt == 0){
        #pragma unroll
        for (int q = 0; q < 3; q++){
            #pragma unroll
            for (int j = 0; j < 4; j++){
                #pragma unroll
                for (int k = 0; k < 2; k++){
                    num[j][k] += red[q*2048 + txq*16 + j*2 + k];
                    den[j][k] += red[q*2048 + txq*16 + j*2 + k + 8];
                }
            }
        }
    }
}

// ---------------------------------------------------------------------------
// Sensory pass: writes A[b,h], Dc[b,h] with all constants folded in.
// ---------------------------------------------------------------------------
__global__ __launch_bounds__(512, 2) void k_sensory(
        const float* __restrict__ inp,
        const float* __restrict__ vleak, const float* __restrict__ gleak,
        const float* __restrict__ cm){
    __shared__ __align__(16) float sp[4][2][4][ICH][64];
    __shared__ float vs[4][2][16][ICH+1];

    const int h0 = blockIdx.x * 64;
    const int b0 = blockIdx.y * 16;
    const int tx = threadIdx.x;

    float num[4][2] = {}, den[4][2] = {};
    mainloop_core<I_SZ/4, I_SZ>(s_SG, s_MS, s_WE, s_WW, inp, h0, b0, tx,
                                num, den, sp, vs);

    if (tx < 128){
        const int lane = tx & 31;
        const int wq   = tx >> 5;
        #pragma unroll
        for (int k = 0; k < 2; k++){
            int h = h0 + 2*lane + k;
            float base_n = fmaf(gleak[h], vleak[h], g_CN[h]);
            float base_d = cm[h] + gleak[h] + g_CD[h];
            #pragma unroll
            for (int j = 0; j < 4; j++){
                int b = b0 + 4*wq + j;
                g_A [b*H_SZ + h] = num[j][k] + base_n;
                g_Dc[b*H_SZ + h] = den[j][k] + base_d;
            }
        }
    }
}

// ---------------------------------------------------------------------------
// One recurrent unfold.
// ---------------------------------------------------------------------------
__global__ __launch_bounds__(512, 2) void k_step(const float* vext, float* voutext,
                                                 int sel_in, int sel_out,
                                                 const float* __restrict__ cm){
    const float* vin  = (sel_in  == 0) ? g_v0 : ((sel_in  == 1) ? g_v1 : vext);
    float*       vout = (sel_out == 0) ? g_v0 : ((sel_out == 1) ? g_v1 : voutext);

    __shared__ __align__(16) float sp[4][2][4][ICH][64];
    __shared__ float vs[4][2][16][ICH+1];

    const int h0 = blockIdx.x * 64;
    const int b0 = blockIdx.y * 16;
    const int tx = threadIdx.x;

    float num[4][2] = {}, den[4][2] = {};
    mainloop_core<H_SZ/4, H_SZ>(g_SG, g_MS, g_WE, g_WW, vin, h0, b0, tx,
                                num, den, sp, vs);

    if (tx < 128){
        const int lane = tx & 31;
        const int wq   = tx >> 5;
        #pragma unroll
        for (int k = 0; k < 2; k++){
            int h = h0 + 2*lane + k;
            float cmh = cm[h];
            #pragma unroll
            for (int j = 0; j < 4; j++){
                int b = b0 + 4*wq + j;
                float n = fmaf(cmh, vin[b*H_SZ + h], g_A[b*H_SZ + h]) + num[j][k];
                float d = g_Dc[b*H_SZ + h] + den[j][k];
                vout[b*H_SZ + h] = __fdividef(n, d + 1e-8f);
            }
        }
    }
}

extern "C" void kernel_launch(void* const* d_in, const int* in_sizes, int n_in,
                              void* d_out, int out_size){
    const float* inputs = (const float*)d_in[0];
    const float* state  = (const float*)d_in[1];
    const float* smu    = (const float*)d_in[2];
    const float* ssig   = (const float*)d_in[3];
    const float* sW     = (const float*)d_in[4];
    const float* serev  = (const float*)d_in[5];
    const float* mu     = (const float*)d_in[6];
    const float* sigma  = (const float*)d_in[7];
    const float* W      = (const float*)d_in[8];
    const float* erev   = (const float*)d_in[9];
    const float* vleak  = (const float*)d_in[10];
    const float* gleak  = (const float*)d_in[11];
    const float* cm     = (const float*)d_in[12];
    float* out = (float*)d_out;

    k_prep<<<((H_SZ+I_SZ)*H_SZ + 255)/256, 256>>>(mu, sigma, W, erev,
                                                  smu, ssig, sW, serev);
    k_colsum<<<H_SZ/32, 256>>>();

    dim3 grid(H_SZ/64, B_SZ/16);   // (8, 32) = 256 blocks, 512 threads each
    k_sensory<<<grid, 512>>>(inputs, vleak, gleak, cm);

    // 6 unfolds: state -> v0 -> v1 -> v0 -> v1 -> v0 -> out
    k_step<<<grid, 512>>>(state,   nullptr, 2, 0, cm);
    k_step<<<grid, 512>>>(nullptr, nullptr, 0, 1, cm);
    k_step<<<grid, 512>>>(nullptr, nullptr, 1, 0, cm);
    k_step<<<grid, 512>>>(nullptr, nullptr, 0, 1, cm);
    k_step<<<grid, 512>>>(nullptr, nullptr, 1, 0, cm);
    k_step<<<grid, 512>>>(nullptr, out,     0, 2, cm);
}

// round 9
// speedup vs baseline: 1.3903x; 1.1177x over previous
#include <cuda_runtime.h>
#include <cstdint>

#define B_SZ 512
#define I_SZ 256
#define H_SZ 512
#define ICH  8

typedef unsigned long long ull;

// Transformed parameter planes (recurrent + sensory) and scratch
__device__ float g_SG[H_SZ*H_SZ];
__device__ float g_MS[H_SZ*H_SZ];
__device__ float g_WE[H_SZ*H_SZ];
__device__ float g_WW[H_SZ*H_SZ];
__device__ float s_SG[I_SZ*H_SZ];
__device__ float s_MS[I_SZ*H_SZ];
__device__ float s_WE[I_SZ*H_SZ];
__device__ float s_WW[I_SZ*H_SZ];
__device__ float g_CN[H_SZ];
__device__ float g_CD[H_SZ];
__device__ float g_A [B_SZ*H_SZ];
__device__ float g_Dc[B_SZ*H_SZ];
__device__ float g_v0[B_SZ*H_SZ];
__device__ float g_v1[B_SZ*H_SZ];

__device__ __forceinline__ float tanh_fast(float x){
    float y;
    asm("tanh.approx.f32 %0, %1;" : "=f"(y) : "f"(x));
    return y;
}
__device__ __forceinline__ ull pack2(float a, float b){
    ull r; asm("mov.b64 %0, {%1, %2};" : "=l"(r) : "f"(a), "f"(b)); return r;
}
__device__ __forceinline__ void unpack2(ull p, float& a, float& b){
    asm("mov.b64 {%0, %1}, %2;" : "=f"(a), "=f"(b) : "l"(p));
}
__device__ __forceinline__ void ffma2(ull& acc, ull a, ull b){
    asm("fma.rn.f32x2 %0, %1, %2, %0;" : "+l"(acc) : "l"(a), "l"(b));
}
__device__ __forceinline__ void fadd2(ull& acc, ull v){
    asm("add.rn.f32x2 %0, %0, %1;" : "+l"(acc) : "l"(v));
}

// sigmoid((v-mu)*sigma) = 0.5*tanh(0.5*sigma*v - 0.5*sigma*mu) + 0.5
__global__ void k_prep(const float* __restrict__ mu, const float* __restrict__ sigma,
                       const float* __restrict__ W,  const float* __restrict__ erev,
                       const float* __restrict__ smu, const float* __restrict__ ssig,
                       const float* __restrict__ sW,  const float* __restrict__ serev){
    int idx = blockIdx.x*blockDim.x + threadIdx.x;
    if (idx < H_SZ*H_SZ){
        float s = sigma[idx], m = mu[idx], w = W[idx], e = erev[idx];
        g_SG[idx] = 0.5f*s;
        g_MS[idx] = -0.5f*s*m;
        g_WE[idx] = 0.5f*w*e;
        g_WW[idx] = 0.5f*w;
    } else if (idx < (H_SZ + I_SZ)*H_SZ){
        int j = idx - H_SZ*H_SZ;
        float s = ssig[j], m = smu[j], w = sW[j], e = serev[j];
        s_SG[j] = 0.5f*s;
        s_MS[j] = -0.5f*s*m;
        s_WE[j] = 0.5f*w*e;
        s_WW[j] = 0.5f*w;
    }
}

// Per-h constants: column sums of WE/WW over recurrent (H) + sensory (I) rows
__global__ void k_colsum(){
    int h0 = blockIdx.x * 32;
    int hh = threadIdx.x & 31;
    int it = threadIdx.x >> 5;
    float sn = 0.f, sd = 0.f;
    for (int i = it; i < H_SZ; i += 8){
        sn += g_WE[i*H_SZ + h0 + hh];
        sd += g_WW[i*H_SZ + h0 + hh];
    }
    for (int i = it; i < I_SZ; i += 8){
        sn += s_WE[i*H_SZ + h0 + hh];
        sd += s_WW[i*H_SZ + h0 + hh];
    }
    __shared__ float rn[8][32], rd[8][32];
    rn[it][hh] = sn; rd[it][hh] = sd;
    __syncthreads();
    if (it == 0){
        float a = 0.f, b = 0.f;
        #pragma unroll
        for (int k = 0; k < 8; k++){ a += rn[k][hh]; b += rd[k][hh]; }
        g_CN[h0+hh] = a; g_CD[h0+hh] = b;
    }
}

// ---------------------------------------------------------------------------
// Main loop core, i-split within block. Tile 64h x 16b, 256 threads
// = 2 halves x 4 warps. Lane covers h = h0+2*lane+{0,1} (conflict-free
// LDS.64 params). Warp-in-half covers 4 batches (one LDS.128 broadcast of v).
// Accumulation in packed f32x2 (FFMA2). Register double-buffer, 1 bar/chunk.
// Result valid for hf==0 threads (tx < 128) after the combine.
// ---------------------------------------------------------------------------
template<int HALF_I, int VSTR>
__device__ __forceinline__ void mainloop_core(
        const float* __restrict__ P0, const float* __restrict__ P1,
        const float* __restrict__ P2, const float* __restrict__ P3,
        const float* __restrict__ vin, int h0, int b0, int tx,
        ull (&num2)[4], ull (&den2)[4],
        float (*sp)[2][4][ICH][64], float (*vs)[2][ICH][16])
{
    const int hf   = tx >> 7;          // half: 0/1
    const int txh  = tx & 127;
    const int lane = tx & 31;
    const int wq   = txh >> 5;         // warp in half: b = b0 + 4*wq + j
    const int ibase = hf * HALF_I;
    const int pic  = txh >> 4;         // 0..7   (prefetch ic)
    const int pq   = (txh & 15) * 4;   // 0..60  (prefetch h-quad)
    const int vb   = txh & 15;         // v: batch row
    const int vic  = txh >> 4;         // v: i within chunk
    const int NC   = HALF_I / ICH;

    float4 r[4];
    float rv;

    auto prefetch = [&](int c){
        int i0 = ibase + c * ICH;
        int g  = (i0 + pic)*H_SZ + h0 + pq;
        r[0] = *(const float4*)&P0[g];
        r[1] = *(const float4*)&P1[g];
        r[2] = *(const float4*)&P2[g];
        r[3] = *(const float4*)&P3[g];
        rv   = vin[(b0 + vb)*VSTR + i0 + vic];
    };
    auto sts = [&](int buf){
        *(float4*)&sp[hf][buf][0][pic][pq] = r[0];
        *(float4*)&sp[hf][buf][1][pic][pq] = r[1];
        *(float4*)&sp[hf][buf][2][pic][pq] = r[2];
        *(float4*)&sp[hf][buf][3][pic][pq] = r[3];
        vs[hf][buf][vic][vb] = rv;
    };

    int buf = 0;
    prefetch(0); sts(0); __syncthreads();

    for (int c = 0; c < NC; c++){
        if (c + 1 < NC) prefetch(c + 1);
        #pragma unroll
        for (int ic = 0; ic < ICH; ic++){
            float2 SG = *(const float2*)&sp[hf][buf][0][ic][2*lane];
            float2 MS = *(const float2*)&sp[hf][buf][1][ic][2*lane];
            ull    WE2 = *(const ull*)&sp[hf][buf][2][ic][2*lane];
            ull    WW2 = *(const ull*)&sp[hf][buf][3][ic][2*lane];
            float4 vv = *(const float4*)&vs[hf][buf][ic][4*wq];
            float vj[4] = {vv.x, vv.y, vv.z, vv.w};
            #pragma unroll
            for (int j = 0; j < 4; j++){
                float t0 = tanh_fast(fmaf(vj[j], SG.x, MS.x));
                float t1 = tanh_fast(fmaf(vj[j], SG.y, MS.y));
                ull t2 = pack2(t0, t1);
                ffma2(num2[j], WE2, t2);
                ffma2(den2[j], WW2, t2);
            }
        }
        if (c + 1 < NC){ sts(buf ^ 1); __syncthreads(); buf ^= 1; }
    }

    // Combine halves: half 1 stores packed partials, half 0 adds them.
    __syncthreads();
    ull* red = (ull*)&sp[0][0][0][0][0];   // 128 threads x 8 x 8B = 8KB reuse
    if (hf == 1){
        #pragma unroll
        for (int j = 0; j < 4; j++){
            red[txh*8 + j]     = num2[j];
            red[txh*8 + 4 + j] = den2[j];
        }
    }
    __syncthreads();
    if (hf == 0){
        #pragma unroll
        for (int j = 0; j < 4; j++){
            fadd2(num2[j], red[txh*8 + j]);
            fadd2(den2[j], red[txh*8 + 4 + j]);
        }
    }
}

// ---------------------------------------------------------------------------
// Sensory pass: writes A[b,h], Dc[b,h] with all constants folded in.
// ---------------------------------------------------------------------------
__global__ __launch_bounds__(256) void k_sensory(
        const float* __restrict__ inp,
        const float* __restrict__ vleak, const float* __restrict__ gleak,
        const float* __restrict__ cm){
    __shared__ __align__(16) float sp[2][2][4][ICH][64];
    __shared__ __align__(16) float vs[2][2][ICH][16];

    const int h0 = blockIdx.x * 64;
    const int b0 = blockIdx.y * 16;
    const int tx = threadIdx.x;

    ull num2[4], den2[4];
    #pragma unroll
    for (int j = 0; j < 4; j++){ num2[j] = 0ull; den2[j] = 0ull; }

    mainloop_core<I_SZ/2, I_SZ>(s_SG, s_MS, s_WE, s_WW, inp, h0, b0, tx,
                                num2, den2, sp, vs);

    if (tx < 128){
        const int lane = tx & 31;
        const int wq   = tx >> 5;
        #pragma unroll
        for (int j = 0; j < 4; j++){
            float n0, n1, d0, d1;
            unpack2(num2[j], n0, n1);
            unpack2(den2[j], d0, d1);
            int b = b0 + 4*wq + j;
            #pragma unroll
            for (int k = 0; k < 2; k++){
                int h = h0 + 2*lane + k;
                float base_n = fmaf(gleak[h], vleak[h], g_CN[h]);
                float base_d = cm[h] + gleak[h] + g_CD[h];
                g_A [b*H_SZ + h] = (k ? n1 : n0) + base_n;
                g_Dc[b*H_SZ + h] = (k ? d1 : d0) + base_d;
            }
        }
    }
}

// ---------------------------------------------------------------------------
// One recurrent unfold.
// ---------------------------------------------------------------------------
__global__ __launch_bounds__(256) void k_step(const float* vext, float* voutext,
                                              int sel_in, int sel_out,
                                              const float* __restrict__ cm){
    const float* vin  = (sel_in  == 0) ? g_v0 : ((sel_in  == 1) ? g_v1 : vext);
    float*       vout = (sel_out == 0) ? g_v0 : ((sel_out == 1) ? g_v1 : voutext);

    __shared__ __align__(16) float sp[2][2][4][ICH][64];
    __shared__ __align__(16) float vs[2][2][ICH][16];

    const int h0 = blockIdx.x * 64;
    const int b0 = blockIdx.y * 16;
    const int tx = threadIdx.x;

    ull num2[4], den2[4];
    #pragma unroll
    for (int j = 0; j < 4; j++){ num2[j] = 0ull; den2[j] = 0ull; }

    mainloop_core<H_SZ/2, H_SZ>(g_SG, g_MS, g_WE, g_WW, vin, h0, b0, tx,
                                num2, den2, sp, vs);

    if (tx < 128){
        const int lane = tx & 31;
        const int wq   = tx >> 5;
        #pragma unroll
        for (int j = 0; j < 4; j++){
            float n0, n1, d0, d1;
            unpack2(num2[j], n0, n1);
            unpack2(den2[j], d0, d1);
            int b = b0 + 4*wq + j;
            #pragma unroll
            for (int k = 0; k < 2; k++){
                int h = h0 + 2*lane + k;
                float cmh = cm[h];
                float n = fmaf(cmh, vin[b*H_SZ + h], g_A[b*H_SZ + h]) + (k ? n1 : n0);
                float d = g_Dc[b*H_SZ + h] + (k ? d1 : d0);
                vout[b*H_SZ + h] = __fdividef(n, d + 1e-8f);
            }
        }
    }
}

extern "C" void kernel_launch(void* const* d_in, const int* in_sizes, int n_in,
                              void* d_out, int out_size){
    const float* inputs = (const float*)d_in[0];
    const float* state  = (const float*)d_in[1];
    const float* smu    = (const float*)d_in[2];
    const float* ssig   = (const float*)d_in[3];
    const float* sW     = (const float*)d_in[4];
    const float* serev  = (const float*)d_in[5];
    const float* mu     = (const float*)d_in[6];
    const float* sigma  = (const float*)d_in[7];
    const float* W      = (const float*)d_in[8];
    const float* erev   = (const float*)d_in[9];
    const float* vleak  = (const float*)d_in[10];
    const float* gleak  = (const float*)d_in[11];
    const float* cm     = (const float*)d_in[12];
    float* out = (float*)d_out;

    k_prep<<<((H_SZ+I_SZ)*H_SZ + 255)/256, 256>>>(mu, sigma, W, erev,
                                                  smu, ssig, sW, serev);
    k_colsum<<<H_SZ/32, 256>>>();

    dim3 grid(H_SZ/64, B_SZ/16);   // (8, 32) = 256 blocks, 256 threads each
    k_sensory<<<grid, 256>>>(inputs, vleak, gleak, cm);

    // 6 unfolds: state -> v0 -> v1 -> v0 -> v1 -> v0 -> out
    k_step<<<grid, 256>>>(state,   nullptr, 2, 0, cm);
    k_step<<<grid, 256>>>(nullptr, nullptr, 0, 1, cm);
    k_step<<<grid, 256>>>(nullptr, nullptr, 1, 0, cm);
    k_step<<<grid, 256>>>(nullptr, nullptr, 0, 1, cm);
    k_step<<<grid, 256>>>(nullptr, nullptr, 1, 0, cm);
    k_step<<<grid, 256>>>(nullptr, out,     0, 2, cm);
}